// round 1
// baseline (speedup 1.0000x reference)
#include <cuda_runtime.h>
#include <math.h>

// Problem constants
#define Bsz   8
#define Tlen  4096
#define Cdim  512
#define Hdim  512
#define Mtot  (Bsz * Tlen)      // 32768 rows
#define Kdim  (2 * Cdim)        // 1024 (conv K=2 flattened)
#define NCH   32                // scan chunks per sequence
#define CHUNK (Tlen / NCH)      // 128 timesteps per chunk

// Scratch (device globals — no allocation allowed in kernel_launch)
__device__ float g_z[(size_t)Mtot * Hdim];   // tanh gate
__device__ float g_f[(size_t)Mtot * Hdim];   // forget gate (sigmoid)
__device__ float g_o[(size_t)Mtot * Hdim];   // output gate (sigmoid)
__device__ float g_P[(size_t)Bsz * NCH * Hdim];    // per-chunk product of f
__device__ float g_L[(size_t)Mtot > 0 ? (size_t)Bsz * NCH * Hdim : 1]; // per-chunk local tail
__device__ float g_hin[(size_t)Bsz * NCH * Hdim];  // per-chunk incoming state

// ---------------------------------------------------------------------------
// GEMM: gates[m, n] = act( sum_kk A[m,kk] * W[kk, n] + bias[n] )
//   A[m, kk] = x[b, t-1, kk]        for kk < 512   (0 if t == 0)
//            = x[b, t,   kk-512]    for kk >= 512
//   W is kernel[k][c][h] viewed as [1024, 512] row-major (stride Hdim).
// blockIdx.z selects gate (0=z/tanh, 1=f/sigmoid, 2=o/sigmoid).
// Tiling: 128x128x8, 256 threads, 8x8 per-thread micro-tile.
// ---------------------------------------------------------------------------
#define BM 128
#define BN 128
#define BK 8

__global__ __launch_bounds__(256, 2) void gate_gemm(
    const float* __restrict__ x,
    const float* __restrict__ wz, const float* __restrict__ bz,
    const float* __restrict__ wf, const float* __restrict__ bf,
    const float* __restrict__ wo, const float* __restrict__ bo)
{
    __shared__ float As[BK][BM];
    __shared__ float Bs[BK][BN];

    const int gate = blockIdx.z;
    const float* __restrict__ W    = (gate == 0) ? wz : ((gate == 1) ? wf : wo);
    const float* __restrict__ bias = (gate == 0) ? bz : ((gate == 1) ? bf : bo);
    float* __restrict__ out        = (gate == 0) ? g_z : ((gate == 1) ? g_f : g_o);

    const int tid = threadIdx.x;
    const int m0  = blockIdx.y * BM;
    const int n0  = blockIdx.x * BN;

    // A-tile load mapping: one float4 per thread per k-step
    const int a_row = tid >> 1;            // 0..127
    const int a_seg = (tid & 1) * 4;       // 0 or 4
    const int m     = m0 + a_row;
    const int b     = m / Tlen;
    const int t     = m % Tlen;

    // B-tile load mapping: one float4 per thread per k-step
    const int b_row = tid >> 5;            // 0..7
    const int b_col = (tid & 31) * 4;      // 0..124

    const int tx = tid & 15;               // n micro index
    const int ty = tid >> 4;               // m micro index

    float acc[8][8];
    #pragma unroll
    for (int i = 0; i < 8; i++)
        #pragma unroll
        for (int j = 0; j < 8; j++) acc[i][j] = 0.0f;

    for (int k0 = 0; k0 < Kdim; k0 += BK) {
        // ---- load tiles to registers ----
        const int kk = k0 + a_seg;
        float4 av;
        if (kk < Cdim) {
            if (t > 0)
                av = *(const float4*)(x + (size_t)(b * Tlen + t - 1) * Cdim + kk);
            else
                av = make_float4(0.f, 0.f, 0.f, 0.f);
        } else {
            av = *(const float4*)(x + (size_t)(b * Tlen + t) * Cdim + (kk - Cdim));
        }
        float4 bv = *(const float4*)(W + (size_t)(k0 + b_row) * Hdim + (n0 + b_col));

        __syncthreads();   // previous iteration's reads are done
        As[a_seg + 0][a_row] = av.x;
        As[a_seg + 1][a_row] = av.y;
        As[a_seg + 2][a_row] = av.z;
        As[a_seg + 3][a_row] = av.w;
        *(float4*)&Bs[b_row][b_col] = bv;
        __syncthreads();

        // ---- compute ----
        #pragma unroll
        for (int kk2 = 0; kk2 < BK; kk2++) {
            float ar[8], br[8];
            #pragma unroll
            for (int i = 0; i < 8; i++) ar[i] = As[kk2][ty + i * 16];
            #pragma unroll
            for (int j = 0; j < 8; j++) br[j] = Bs[kk2][tx + j * 16];
            #pragma unroll
            for (int i = 0; i < 8; i++)
                #pragma unroll
                for (int j = 0; j < 8; j++)
                    acc[i][j] = fmaf(ar[i], br[j], acc[i][j]);
        }
    }

    // ---- epilogue: bias + activation + store ----
    #pragma unroll
    for (int i = 0; i < 8; i++) {
        const int mm = m0 + ty + i * 16;
        #pragma unroll
        for (int j = 0; j < 8; j++) {
            const int nn = n0 + tx + j * 16;
            float v = acc[i][j] + bias[nn];
            if (gate == 0)
                v = tanhf(v);
            else
                v = 1.0f / (1.0f + expf(-v));
            out[(size_t)mm * Hdim + nn] = v;
        }
    }
}

// ---------------------------------------------------------------------------
// Scan phase 1: per (b, h, chunk) compute P = prod(f) and L = local scan tail
// ---------------------------------------------------------------------------
__global__ __launch_bounds__(Hdim) void chunk_reduce()
{
    const int h = threadIdx.x;      // 0..511
    const int c = blockIdx.x;       // 0..NCH-1
    const int b = blockIdx.y;       // 0..Bsz-1

    size_t base = (size_t)(b * Tlen + c * CHUNK) * Hdim + h;
    float P = 1.0f, L = 0.0f;
    #pragma unroll 4
    for (int i = 0; i < CHUNK; i++) {
        const size_t idx = base + (size_t)i * Hdim;
        const float f = g_f[idx];
        const float z = g_z[idx];
        L = fmaf(f, L, (1.0f - f) * z);
        P *= f;
    }
    const size_t cidx = (size_t)(b * NCH + c) * Hdim + h;
    g_P[cidx] = P;
    g_L[cidx] = L;
}

// ---------------------------------------------------------------------------
// Scan phase 2: serial prefix over the NCH chunk carries (tiny)
// ---------------------------------------------------------------------------
__global__ __launch_bounds__(Hdim) void chunk_prefix()
{
    const int h = threadIdx.x;
    const int b = blockIdx.x;
    float hc = 0.0f;
    for (int c = 0; c < NCH; c++) {
        const size_t idx = (size_t)(b * NCH + c) * Hdim + h;
        g_hin[idx] = hc;
        hc = fmaf(g_P[idx], hc, g_L[idx]);
    }
}

// ---------------------------------------------------------------------------
// Scan phase 3: rerun local scans with correct incoming state, apply o-gate
// ---------------------------------------------------------------------------
__global__ __launch_bounds__(Hdim) void chunk_apply(float* __restrict__ out)
{
    const int h = threadIdx.x;
    const int c = blockIdx.x;
    const int b = blockIdx.y;

    float hc = g_hin[(size_t)(b * NCH + c) * Hdim + h];
    size_t base = (size_t)(b * Tlen + c * CHUNK) * Hdim + h;
    #pragma unroll 4
    for (int i = 0; i < CHUNK; i++) {
        const size_t idx = base + (size_t)i * Hdim;
        const float f = g_f[idx];
        const float z = g_z[idx];
        const float o = g_o[idx];
        hc = fmaf(f, hc, (1.0f - f) * z);
        out[idx] = hc * o;
    }
}

// ---------------------------------------------------------------------------
extern "C" void kernel_launch(void* const* d_in, const int* in_sizes, int n_in,
                              void* d_out, int out_size)
{
    const float* x  = (const float*)d_in[0];
    const float* wz = (const float*)d_in[1];
    const float* bz = (const float*)d_in[2];
    const float* wf = (const float*)d_in[3];
    const float* bf = (const float*)d_in[4];
    const float* wo = (const float*)d_in[5];
    const float* bo = (const float*)d_in[6];
    float* out = (float*)d_out;

    dim3 gemm_grid(Hdim / BN, Mtot / BM, 3);   // (4, 256, 3)
    gate_gemm<<<gemm_grid, 256>>>(x, wz, bz, wf, bf, wo, bo);

    chunk_reduce<<<dim3(NCH, Bsz), Hdim>>>();
    chunk_prefix<<<Bsz, Hdim>>>();
    chunk_apply<<<dim3(NCH, Bsz), Hdim>>>(out);
}

// round 4
// speedup vs baseline: 2.1843x; 2.1843x over previous
#include <cuda_runtime.h>
#include <cuda_bf16.h>
#include <stdint.h>
#include <math.h>

// ---------------- problem constants ----------------
#define Bsz   8
#define Tlen  4096
#define Cdim  512
#define Hdim  512
#define Mtot  (Bsz * Tlen)          // 32768 rows
#define NCH   32
#define CHUNK (Tlen / NCH)

// ---------------- GEMM tiling ----------------
#define BM     128
#define BN     128
#define BK     32                   // bf16 K per stage
#define STAGES 4
#define NIT    96                   // 3 terms * (1024/32)
#define AROWB  80                   // padded smem row stride (bytes), 16B-aligned
#define ASTG   (BM * AROWB)         // 10240
#define BSTG   (BN * AROWB)         // 10240
#define STG    (ASTG + BSTG)        // 20480
#define SMEMT  (STAGES * STG)       // 81920

// ---------------- device scratch ----------------
__device__ float g_z[(size_t)Mtot * Hdim];
__device__ float g_f[(size_t)Mtot * Hdim];
__device__ float g_o[(size_t)Mtot * Hdim];
__device__ float g_P[Bsz * NCH * Hdim];
__device__ float g_L[Bsz * NCH * Hdim];
__device__ float g_hin[Bsz * NCH * Hdim];
__device__ __nv_bfloat16 g_xhi[(size_t)Mtot * Cdim];
__device__ __nv_bfloat16 g_xlo[(size_t)Mtot * Cdim];
__device__ __nv_bfloat16 g_wthi[3][(size_t)Hdim * 2 * Cdim];  // [gate][h*1024 + kk]
__device__ __nv_bfloat16 g_wtlo[3][(size_t)Hdim * 2 * Cdim];

// ---------------- PTX helpers ----------------
__device__ __forceinline__ uint32_t smem_u32(const void* p) {
    uint32_t a;
    asm("{ .reg .u64 t; cvta.to.shared.u64 t, %1; cvt.u32.u64 %0, t; }" : "=r"(a) : "l"(p));
    return a;
}
__device__ __forceinline__ void cpa16(uint32_t dst, const void* src, uint32_t sz) {
    asm volatile("cp.async.cg.shared.global [%0], [%1], 16, %2;"
                 :: "r"(dst), "l"(src), "r"(sz) : "memory");
}
#define CP_COMMIT() asm volatile("cp.async.commit_group;" ::: "memory")
#define CP_WAIT2()  asm volatile("cp.async.wait_group 2;" ::: "memory")

#define LDSM4(r, a) \
    asm volatile("ldmatrix.sync.aligned.m8n8.x4.shared.b16 {%0,%1,%2,%3}, [%4];" \
        : "=r"((r)[0]), "=r"((r)[1]), "=r"((r)[2]), "=r"((r)[3]) : "r"(a))

__device__ __forceinline__ void mma16816(float* c, const uint32_t* a,
                                         uint32_t b0, uint32_t b1) {
    asm volatile(
        "mma.sync.aligned.m16n8k16.row.col.f32.bf16.bf16.f32 "
        "{%0,%1,%2,%3}, {%4,%5,%6,%7}, {%8,%9}, {%0,%1,%2,%3};"
        : "+f"(c[0]), "+f"(c[1]), "+f"(c[2]), "+f"(c[3])
        : "r"(a[0]), "r"(a[1]), "r"(a[2]), "r"(a[3]), "r"(b0), "r"(b1));
}

// ---------------- prep kernels ----------------
__global__ __launch_bounds__(256) void prep_x(const float* __restrict__ x) {
    size_t i = (size_t)blockIdx.x * 256 + threadIdx.x;   // over Mtot*Cdim/4
    float4 v = ((const float4*)x)[i];
    __nv_bfloat16 h0 = __float2bfloat16(v.x), h1 = __float2bfloat16(v.y);
    __nv_bfloat16 h2 = __float2bfloat16(v.z), h3 = __float2bfloat16(v.w);
    __nv_bfloat16 l0 = __float2bfloat16(v.x - __bfloat162float(h0));
    __nv_bfloat16 l1 = __float2bfloat16(v.y - __bfloat162float(h1));
    __nv_bfloat16 l2 = __float2bfloat16(v.z - __bfloat162float(h2));
    __nv_bfloat16 l3 = __float2bfloat16(v.w - __bfloat162float(h3));
    __nv_bfloat162* hp = (__nv_bfloat162*)g_xhi;
    __nv_bfloat162* lp = (__nv_bfloat162*)g_xlo;
    hp[i*2]   = __nv_bfloat162(h0, h1);
    hp[i*2+1] = __nv_bfloat162(h2, h3);
    lp[i*2]   = __nv_bfloat162(l0, l1);
    lp[i*2+1] = __nv_bfloat162(l2, l3);
}

// transpose W [1024,512] f32 -> Wt [512,1024] bf16 hi/lo
__global__ __launch_bounds__(256) void prep_w(
    const float* __restrict__ wz, const float* __restrict__ wf, const float* __restrict__ wo)
{
    __shared__ float tile[32][33];
    const int gate = blockIdx.z;
    const float* W = (gate == 0) ? wz : ((gate == 1) ? wf : wo);
    const int kk0 = blockIdx.x * 32, h0 = blockIdx.y * 32;
    const int tx = threadIdx.x & 31, ty = threadIdx.x >> 5;   // 32 x 8
    for (int i = ty; i < 32; i += 8)
        tile[i][tx] = W[(size_t)(kk0 + i) * Hdim + h0 + tx];
    __syncthreads();
    for (int i = ty; i < 32; i += 8) {
        float v = tile[tx][i];                                 // W[kk0+tx][h0+i]
        __nv_bfloat16 hi = __float2bfloat16(v);
        __nv_bfloat16 lo = __float2bfloat16(v - __bfloat162float(hi));
        size_t oi = (size_t)(h0 + i) * 1024 + kk0 + tx;
        g_wthi[gate][oi] = hi;
        g_wtlo[gate][oi] = lo;
    }
}

// ---------------- HMMA GEMM ----------------
// grid (N/BN=4, M/BM=256, 3 gates), 256 threads (8 warps as 4m x 2n)
__global__ __launch_bounds__(256, 2) void gate_gemm_mma(
    const float* __restrict__ bz, const float* __restrict__ bf_,
    const float* __restrict__ bo)
{
    extern __shared__ char smem[];
    const uint32_t sb = smem_u32(smem);
    const int tid = threadIdx.x, lane = tid & 31, wid = tid >> 5;
    const int wm = wid & 3, wn = wid >> 2;
    const int gate = blockIdx.z;
    const int n0 = blockIdx.x * BN;
    const int m0 = blockIdx.y * BM;

    const float* bias = (gate == 0) ? bz : ((gate == 1) ? bf_ : bo);
    float* outg       = (gate == 0) ? g_z : ((gate == 1) ? g_f : g_o);
    const __nv_bfloat16* whi = g_wthi[gate];
    const __nv_bfloat16* wlo = g_wtlo[gate];

    const int arow = tid >> 2;        // 0..63 (two rows: arow, arow+64)
    const int aseg = tid & 3;         // 16B segment within 64B row

    auto load_stage = [&](int it) {
        const int term = it >> 5;                 // 0: hi*hi, 1: hi*lo, 2: lo*hi
        const int kidx = (it & 31) * 32;          // 0..992
        const __nv_bfloat16* Ap = (term == 2) ? g_xlo : g_xhi;
        const __nv_bfloat16* Wp = (term == 1) ? wlo : whi;
        const int shift = (kidx < 512) ? 1 : 0;   // tap t-1 vs t
        const int acolB = ((kidx & 511) * 2) + aseg * 16;
        const int wcolB = kidx * 2 + aseg * 16;
        const uint32_t as = sb + (it & (STAGES - 1)) * STG;
        const uint32_t bs = as + ASTG;
        #pragma unroll
        for (int h = 0; h < 2; h++) {
            const int r = arow + h * 64;
            const int m = m0 + r;
            const char* src = (const char*)Ap + (size_t)(m - shift) * 1024 + acolB;
            uint32_t sz = 16;
            if (shift && ((m & (Tlen - 1)) == 0)) { sz = 0; src = (const char*)Ap; }
            cpa16(as + r * AROWB + aseg * 16, src, sz);
        }
        #pragma unroll
        for (int h = 0; h < 2; h++) {
            const int r = arow + h * 64;
            const char* src = (const char*)Wp + (size_t)(n0 + r) * 2048 + wcolB;
            cpa16(bs + r * AROWB + aseg * 16, src, 16);
        }
    };

    load_stage(0); CP_COMMIT();
    load_stage(1); CP_COMMIT();
    load_stage(2); CP_COMMIT();

    float acc[2][8][4];
    #pragma unroll
    for (int f = 0; f < 2; f++)
        #pragma unroll
        for (int n = 0; n < 8; n++)
            #pragma unroll
            for (int q = 0; q < 4; q++) acc[f][n][q] = 0.0f;

    // per-lane ldmatrix base offsets
    const uint32_t aBase = (uint32_t)((wm * 32 + (lane & 15)) * AROWB + (lane >> 4) * 16);
    const uint32_t bBase = (uint32_t)((wn * 64 + (lane & 15)) * AROWB + (lane >> 4) * 16);

    for (int it = 0; it < NIT; it++) {
        CP_WAIT2();
        __syncthreads();
        const uint32_t as = sb + (it & (STAGES - 1)) * STG;
        const uint32_t bs = as + ASTG;
        #pragma unroll
        for (int jk = 0; jk < 2; jk++) {
            uint32_t af[2][4], bg[4][4];
            LDSM4(af[0], as + aBase + jk * 32);
            LDSM4(af[1], as + aBase + 16 * AROWB + jk * 32);
            #pragma unroll
            for (int g = 0; g < 4; g++)
                LDSM4(bg[g], bs + bBase + g * 16 * AROWB + jk * 32);
            #pragma unroll
            for (int f = 0; f < 2; f++)
                #pragma unroll
                for (int nt = 0; nt < 8; nt++) {
                    const int g = nt >> 1, p = nt & 1;
                    mma16816(acc[f][nt], af[f], bg[g][p], bg[g][p + 2]);
                }
        }
        __syncthreads();
        if (it + 3 < NIT) load_stage(it + 3);
        CP_COMMIT();
    }

    // epilogue: bias + activation + direct stores
    #pragma unroll
    for (int f = 0; f < 2; f++) {
        const int rbase = m0 + wm * 32 + f * 16 + (lane >> 2);
        #pragma unroll
        for (int nt = 0; nt < 8; nt++) {
            const int col = n0 + wn * 64 + nt * 8 + (lane & 3) * 2;
            const float b0 = __ldg(bias + col), b1 = __ldg(bias + col + 1);
            float v0 = acc[f][nt][0] + b0, v1 = acc[f][nt][1] + b1;
            float v2 = acc[f][nt][2] + b0, v3 = acc[f][nt][3] + b1;
            if (gate == 0) {
                v0 = tanhf(v0); v1 = tanhf(v1); v2 = tanhf(v2); v3 = tanhf(v3);
            } else {
                v0 = 1.0f / (1.0f + __expf(-v0));
                v1 = 1.0f / (1.0f + __expf(-v1));
                v2 = 1.0f / (1.0f + __expf(-v2));
                v3 = 1.0f / (1.0f + __expf(-v3));
            }
            float2 lo = make_float2(v0, v1), hi = make_float2(v2, v3);
            *(float2*)(outg + (size_t)rbase * Hdim + col) = lo;
            *(float2*)(outg + (size_t)(rbase + 8) * Hdim + col) = hi;
        }
    }
}

// ---------------- scan (chunked linear recurrence) ----------------
__global__ __launch_bounds__(Hdim) void chunk_reduce()
{
    const int h = threadIdx.x, c = blockIdx.x, b = blockIdx.y;
    size_t base = (size_t)(b * Tlen + c * CHUNK) * Hdim + h;
    float P = 1.0f, L = 0.0f;
    #pragma unroll 4
    for (int i = 0; i < CHUNK; i++) {
        const size_t idx = base + (size_t)i * Hdim;
        const float f = g_f[idx], z = g_z[idx];
        L = fmaf(f, L, (1.0f - f) * z);
        P *= f;
    }
    const size_t ci = (size_t)(b * NCH + c) * Hdim + h;
    g_P[ci] = P; g_L[ci] = L;
}

__global__ __launch_bounds__(Hdim) void chunk_prefix()
{
    const int h = threadIdx.x, b = blockIdx.x;
    float hc = 0.0f;
    for (int c = 0; c < NCH; c++) {
        const size_t idx = (size_t)(b * NCH + c) * Hdim + h;
        g_hin[idx] = hc;
        hc = fmaf(g_P[idx], hc, g_L[idx]);
    }
}

__global__ __launch_bounds__(Hdim) void chunk_apply(float* __restrict__ out)
{
    const int h = threadIdx.x, c = blockIdx.x, b = blockIdx.y;
    float hc = g_hin[(size_t)(b * NCH + c) * Hdim + h];
    size_t base = (size_t)(b * Tlen + c * CHUNK) * Hdim + h;
    #pragma unroll 4
    for (int i = 0; i < CHUNK; i++) {
        const size_t idx = base + (size_t)i * Hdim;
        const float f = g_f[idx], z = g_z[idx], o = g_o[idx];
        hc = fmaf(f, hc, (1.0f - f) * z);
        out[idx] = hc * o;
    }
}

// ---------------- launch ----------------
extern "C" void kernel_launch(void* const* d_in, const int* in_sizes, int n_in,
                              void* d_out, int out_size)
{
    const float* x  = (const float*)d_in[0];
    const float* wz = (const float*)d_in[1];
    const float* bz = (const float*)d_in[2];
    const float* wf = (const float*)d_in[3];
    const float* bf = (const float*)d_in[4];
    const float* wo = (const float*)d_in[5];
    const float* bo = (const float*)d_in[6];
    float* out = (float*)d_out;

    cudaFuncSetAttribute(gate_gemm_mma, cudaFuncAttributeMaxDynamicSharedMemorySize, SMEMT);

    prep_x<<<(size_t)Mtot * Cdim / 4 / 256, 256>>>(x);
    prep_w<<<dim3(1024 / 32, Hdim / 32, 3), 256>>>(wz, wf, wo);

    gate_gemm_mma<<<dim3(Hdim / BN, Mtot / BM, 3), 256, SMEMT>>>(bz, bf, bo);

    chunk_reduce<<<dim3(NCH, Bsz), Hdim>>>();
    chunk_prefix<<<Bsz, Hdim>>>();
    chunk_apply<<<dim3(NCH, Bsz), Hdim>>>(out);
}

// round 5
// speedup vs baseline: 3.1936x; 1.4621x over previous
#include <cuda_runtime.h>
#include <cuda_fp16.h>
#include <stdint.h>
#include <math.h>

// ---------------- problem constants ----------------
#define Bsz   8
#define Tlen  4096
#define Cdim  512
#define Hdim  512
#define Mtot  (Bsz * Tlen)          // 32768 rows
#define NCH   32
#define CHUNK (Tlen / NCH)

// ---------------- GEMM tiling ----------------
#define BM     128
#define BN     128
#define BK     32                   // fp16 K per stage
#define STAGES 4
#define NIT    64                   // 2 terms * (1024/32)
#define AROWB  80                   // padded smem row stride (bytes)
#define ASTG   (BM * AROWB)         // 10240
#define BSTG   (BN * AROWB)         // 10240
#define STG    (ASTG + BSTG)        // 20480
#define SMEMT  (STAGES * STG)       // 81920

// ---------------- device scratch ----------------
__device__ float g_z[(size_t)Mtot * Hdim];
__device__ float g_f[(size_t)Mtot * Hdim];
__device__ float g_o[(size_t)Mtot * Hdim];
__device__ float g_P[Bsz * NCH * Hdim];
__device__ float g_L[Bsz * NCH * Hdim];
__device__ float g_hin[Bsz * NCH * Hdim];
__device__ __half g_xhi[(size_t)Mtot * Cdim];
__device__ __half g_xlo[(size_t)Mtot * Cdim];
__device__ __half g_wt[3][(size_t)Hdim * 2 * Cdim];   // [gate][h*1024 + kk], fp16

// ---------------- PTX helpers ----------------
__device__ __forceinline__ uint32_t smem_u32(const void* p) {
    uint32_t a;
    asm("{ .reg .u64 t; cvta.to.shared.u64 t, %1; cvt.u32.u64 %0, t; }" : "=r"(a) : "l"(p));
    return a;
}
__device__ __forceinline__ void cpa16(uint32_t dst, const void* src, uint32_t sz) {
    asm volatile("cp.async.cg.shared.global [%0], [%1], 16, %2;"
                 :: "r"(dst), "l"(src), "r"(sz) : "memory");
}
#define CP_COMMIT() asm volatile("cp.async.commit_group;" ::: "memory")
#define CP_WAIT2()  asm volatile("cp.async.wait_group 2;" ::: "memory")

#define LDSM4(r, a) \
    asm volatile("ldmatrix.sync.aligned.m8n8.x4.shared.b16 {%0,%1,%2,%3}, [%4];" \
        : "=r"((r)[0]), "=r"((r)[1]), "=r"((r)[2]), "=r"((r)[3]) : "r"(a))

__device__ __forceinline__ void mma16816(float* c, const uint32_t* a,
                                         uint32_t b0, uint32_t b1) {
    asm volatile(
        "mma.sync.aligned.m16n8k16.row.col.f32.f16.f16.f32 "
        "{%0,%1,%2,%3}, {%4,%5,%6,%7}, {%8,%9}, {%0,%1,%2,%3};"
        : "+f"(c[0]), "+f"(c[1]), "+f"(c[2]), "+f"(c[3])
        : "r"(a[0]), "r"(a[1]), "r"(a[2]), "r"(a[3]), "r"(b0), "r"(b1));
}

// ---------------- prep kernels ----------------
__global__ __launch_bounds__(256) void prep_x(const float* __restrict__ x) {
    size_t i = (size_t)blockIdx.x * 256 + threadIdx.x;   // over Mtot*Cdim/4
    float4 v = ((const float4*)x)[i];
    __half h0 = __float2half(v.x), h1 = __float2half(v.y);
    __half h2 = __float2half(v.z), h3 = __float2half(v.w);
    __half l0 = __float2half(v.x - __half2float(h0));
    __half l1 = __float2half(v.y - __half2float(h1));
    __half l2 = __float2half(v.z - __half2float(h2));
    __half l3 = __float2half(v.w - __half2float(h3));
    __half2* hp = (__half2*)g_xhi;
    __half2* lp = (__half2*)g_xlo;
    hp[i*2]   = __half2(h0, h1);
    hp[i*2+1] = __half2(h2, h3);
    lp[i*2]   = __half2(l0, l1);
    lp[i*2+1] = __half2(l2, l3);
}

// transpose W [1024,512] f32 -> Wt [512,1024] fp16
__global__ __launch_bounds__(256) void prep_w(
    const float* __restrict__ wz, const float* __restrict__ wf, const float* __restrict__ wo)
{
    __shared__ float tile[32][33];
    const int gate = blockIdx.z;
    const float* W = (gate == 0) ? wz : ((gate == 1) ? wf : wo);
    const int kk0 = blockIdx.x * 32, h0 = blockIdx.y * 32;
    const int tx = threadIdx.x & 31, ty = threadIdx.x >> 5;   // 32 x 8
    for (int i = ty; i < 32; i += 8)
        tile[i][tx] = W[(size_t)(kk0 + i) * Hdim + h0 + tx];
    __syncthreads();
    for (int i = ty; i < 32; i += 8) {
        float v = tile[tx][i];                                 // W[kk0+tx][h0+i]
        g_wt[gate][(size_t)(h0 + i) * 1024 + kk0 + tx] = __float2half(v);
    }
}

// ---------------- HMMA GEMM ----------------
// grid (N/BN=4, M/BM=256, 3 gates), 256 threads (8 warps as 4m x 2n)
__global__ __launch_bounds__(256, 2) void gate_gemm_mma(
    const float* __restrict__ bz, const float* __restrict__ bf_,
    const float* __restrict__ bo)
{
    extern __shared__ char smem[];
    const uint32_t sb = smem_u32(smem);
    const int tid = threadIdx.x, lane = tid & 31, wid = tid >> 5;
    const int wm = wid & 3, wn = wid >> 2;
    const int gate = blockIdx.z;
    const int n0 = blockIdx.x * BN;
    const int m0 = blockIdx.y * BM;

    const float* bias = (gate == 0) ? bz : ((gate == 1) ? bf_ : bo);
    float* outg       = (gate == 0) ? g_z : ((gate == 1) ? g_f : g_o);
    const __half* wt = g_wt[gate];

    const int arow = tid >> 2;        // 0..63 (two rows: arow, arow+64)
    const int aseg = tid & 3;         // 16B segment within 64B row

    auto load_stage = [&](int it) {
        const int term = it >> 5;                 // 0: hi(A), 1: lo(A)
        const int kidx = (it & 31) * 32;          // 0..992
        const __half* Ap = term ? g_xlo : g_xhi;
        const int shift = (kidx < 512) ? 1 : 0;   // tap t-1 vs t
        const int acolB = ((kidx & 511) * 2) + aseg * 16;
        const int wcolB = kidx * 2 + aseg * 16;
        const uint32_t as = sb + (it & (STAGES - 1)) * STG;
        const uint32_t bs = as + ASTG;
        #pragma unroll
        for (int h = 0; h < 2; h++) {
            const int r = arow + h * 64;
            const int m = m0 + r;
            const char* src = (const char*)Ap + (size_t)(m - shift) * 1024 + acolB;
            uint32_t sz = 16;
            if (shift && ((m & (Tlen - 1)) == 0)) { sz = 0; src = (const char*)Ap; }
            cpa16(as + r * AROWB + aseg * 16, src, sz);
        }
        #pragma unroll
        for (int h = 0; h < 2; h++) {
            const int r = arow + h * 64;
            const char* src = (const char*)wt + (size_t)(n0 + r) * 2048 + wcolB;
            cpa16(bs + r * AROWB + aseg * 16, src, 16);
        }
    };

    load_stage(0); CP_COMMIT();
    load_stage(1); CP_COMMIT();
    load_stage(2); CP_COMMIT();

    float acc[2][8][4];
    #pragma unroll
    for (int f = 0; f < 2; f++)
        #pragma unroll
        for (int n = 0; n < 8; n++)
            #pragma unroll
            for (int q = 0; q < 4; q++) acc[f][n][q] = 0.0f;

    // per-lane ldmatrix base offsets
    const uint32_t aBase = (uint32_t)((wm * 32 + (lane & 15)) * AROWB + (lane >> 4) * 16);
    const uint32_t bBase = (uint32_t)((wn * 64 + (lane & 15)) * AROWB + (lane >> 4) * 16);

    for (int it = 0; it < NIT; it++) {
        CP_WAIT2();
        __syncthreads();
        // issue next stage's loads BEFORE compute: slot (it+3)&3 == (it-1)&3,
        // whose reads all completed before the barrier above.
        if (it + 3 < NIT) load_stage(it + 3);
        CP_COMMIT();

        const uint32_t as = sb + (it & (STAGES - 1)) * STG;
        const uint32_t bs = as + ASTG;
        #pragma unroll
        for (int jk = 0; jk < 2; jk++) {
            uint32_t af[2][4], bg[4][4];
            LDSM4(af[0], as + aBase + jk * 32);
            LDSM4(af[1], as + aBase + 16 * AROWB + jk * 32);
            #pragma unroll
            for (int g = 0; g < 4; g++)
                LDSM4(bg[g], bs + bBase + g * 16 * AROWB + jk * 32);
            #pragma unroll
            for (int f = 0; f < 2; f++)
                #pragma unroll
                for (int nt = 0; nt < 8; nt++) {
                    const int g = nt >> 1, p = nt & 1;
                    mma16816(acc[f][nt], af[f], bg[g][p], bg[g][p + 2]);
                }
        }
    }

    // epilogue: bias + activation + direct stores
    #pragma unroll
    for (int f = 0; f < 2; f++) {
        const int rbase = m0 + wm * 32 + f * 16 + (lane >> 2);
        #pragma unroll
        for (int nt = 0; nt < 8; nt++) {
            const int col = n0 + wn * 64 + nt * 8 + (lane & 3) * 2;
            const float b0 = __ldg(bias + col), b1 = __ldg(bias + col + 1);
            float v0 = acc[f][nt][0] + b0, v1 = acc[f][nt][1] + b1;
            float v2 = acc[f][nt][2] + b0, v3 = acc[f][nt][3] + b1;
            if (gate == 0) {
                v0 = tanhf(v0); v1 = tanhf(v1); v2 = tanhf(v2); v3 = tanhf(v3);
            } else {
                v0 = 1.0f / (1.0f + __expf(-v0));
                v1 = 1.0f / (1.0f + __expf(-v1));
                v2 = 1.0f / (1.0f + __expf(-v2));
                v3 = 1.0f / (1.0f + __expf(-v3));
            }
            float2 lo = make_float2(v0, v1), hi = make_float2(v2, v3);
            *(float2*)(outg + (size_t)rbase * Hdim + col) = lo;
            *(float2*)(outg + (size_t)(rbase + 8) * Hdim + col) = hi;
        }
    }
}

// ---------------- scan (chunked linear recurrence) ----------------
__global__ __launch_bounds__(Hdim) void chunk_reduce()
{
    const int h = threadIdx.x, c = blockIdx.x, b = blockIdx.y;
    size_t base = (size_t)(b * Tlen + c * CHUNK) * Hdim + h;
    float P = 1.0f, L = 0.0f;
    #pragma unroll 4
    for (int i = 0; i < CHUNK; i++) {
        const size_t idx = base + (size_t)i * Hdim;
        const float f = g_f[idx], z = g_z[idx];
        L = fmaf(f, L, (1.0f - f) * z);
        P *= f;
    }
    const size_t ci = (size_t)(b * NCH + c) * Hdim + h;
    g_P[ci] = P; g_L[ci] = L;
}

__global__ __launch_bounds__(Hdim) void chunk_prefix()
{
    const int h = threadIdx.x, b = blockIdx.x;
    float hc = 0.0f;
    for (int c = 0; c < NCH; c++) {
        const size_t idx = (size_t)(b * NCH + c) * Hdim + h;
        g_hin[idx] = hc;
        hc = fmaf(g_P[idx], hc, g_L[idx]);
    }
}

__global__ __launch_bounds__(Hdim) void chunk_apply(float* __restrict__ out)
{
    const int h = threadIdx.x, c = blockIdx.x, b = blockIdx.y;
    float hc = g_hin[(size_t)(b * NCH + c) * Hdim + h];
    size_t base = (size_t)(b * Tlen + c * CHUNK) * Hdim + h;
    #pragma unroll 4
    for (int i = 0; i < CHUNK; i++) {
        const size_t idx = base + (size_t)i * Hdim;
        const float f = g_f[idx], z = g_z[idx], o = g_o[idx];
        hc = fmaf(f, hc, (1.0f - f) * z);
        out[idx] = hc * o;
    }
}

// ---------------- launch ----------------
extern "C" void kernel_launch(void* const* d_in, const int* in_sizes, int n_in,
                              void* d_out, int out_size)
{
    const float* x  = (const float*)d_in[0];
    const float* wz = (const float*)d_in[1];
    const float* bz = (const float*)d_in[2];
    const float* wf = (const float*)d_in[3];
    const float* bf = (const float*)d_in[4];
    const float* wo = (const float*)d_in[5];
    const float* bo = (const float*)d_in[6];
    float* out = (float*)d_out;

    cudaFuncSetAttribute(gate_gemm_mma, cudaFuncAttributeMaxDynamicSharedMemorySize, SMEMT);

    prep_x<<<(size_t)Mtot * Cdim / 4 / 256, 256>>>(x);
    prep_w<<<dim3(1024 / 32, Hdim / 32, 3), 256>>>(wz, wf, wo);

    gate_gemm_mma<<<dim3(Hdim / BN, Mtot / BM, 3), 256, SMEMT>>>(bz, bf, bo);

    chunk_reduce<<<dim3(NCH, Bsz), Hdim>>>();
    chunk_prefix<<<Bsz, Hdim>>>();
    chunk_apply<<<dim3(NCH, Bsz), Hdim>>>(out);
}